// round 1
// baseline (speedup 1.0000x reference)
#include <cuda_runtime.h>
#include <cuda_bf16.h>
#include <cstdint>

// Problem constants (fixed by the reference generator)
#define NN 100000
#define EE 1600000
#define HH 64
#define GG 256

// ---------------- static device scratch (no runtime allocation) ----------------
__device__ float g_dinv[NN];          // deg -> rsqrt(deg)
__device__ float g_norm[EE];          // per-edge norm = dinv[row]*dinv[col]
__device__ float g_bufA[(size_t)NN * HH];   // h_lin scratch
__device__ float g_bufB[(size_t)NN * HH];   // h_in / h_agg ping-pong
__device__ float g_pool[GG * HH];
__device__ float g_cnt[GG];

// ---------------- degree / norm ----------------
__global__ void init_deg_kernel() {
    int i = blockIdx.x * blockDim.x + threadIdx.x;
    if (i < NN) g_dinv[i] = 1.0f;   // self-loop contributes 1 to degree
}

__global__ void accum_deg_kernel(const int* __restrict__ col) {
    int e = blockIdx.x * blockDim.x + threadIdx.x;
    if (e < EE) atomicAdd(&g_dinv[col[e]], 1.0f);
}

__global__ void finish_dinv_kernel() {
    int i = blockIdx.x * blockDim.x + threadIdx.x;
    if (i < NN) g_dinv[i] = rsqrtf(g_dinv[i]);   // deg >= 1 always (self-loop)
}

__global__ void compute_norm_kernel(const int* __restrict__ row,
                                    const int* __restrict__ col) {
    int e = blockIdx.x * blockDim.x + threadIdx.x;
    if (e < EE) g_norm[e] = g_dinv[row[e]] * g_dinv[col[e]];
}

// ---------------- GEMM: lin = act(in) @ W ; agg_init = lin*dinv^2 + b ----------
// Block: 256 threads, 64 rows. Thread computes 4 rows x 4 cols.
__global__ void __launch_bounds__(256)
gemm_kernel(const float* __restrict__ in, const float* __restrict__ W,
            const float* __restrict__ b, float* __restrict__ lin,
            float* __restrict__ agg, int relu_in) {
    __shared__ float Ws[64][64];     // row-major, 16B-aligned rows -> LDS.128 ok
    __shared__ float As[64][65];     // padded to kill bank conflicts on column reads

    int tid = threadIdx.x;
    int r0  = blockIdx.x * 64;

    // Load W (64x64)
    #pragma unroll 4
    for (int i = tid; i < 64 * 64; i += 256)
        Ws[i >> 6][i & 63] = W[i];

    // Load A tile (64 rows), fusing ReLU of the previous layer
    #pragma unroll 4
    for (int i = tid; i < 64 * 64; i += 256) {
        int rr = i >> 6, cc = i & 63;
        int gr = r0 + rr;
        float v = 0.0f;
        if (gr < NN) v = in[(size_t)gr * HH + cc];
        if (relu_in) v = fmaxf(v, 0.0f);
        As[rr][cc] = v;
    }
    __syncthreads();

    int rg = tid >> 4;        // 16 row-groups of 4 rows
    int cg = tid & 15;        // 16 col-groups of 4 cols

    float acc[4][4];
    #pragma unroll
    for (int i = 0; i < 4; i++)
        #pragma unroll
        for (int j = 0; j < 4; j++) acc[i][j] = 0.0f;

    #pragma unroll 8
    for (int k = 0; k < 64; k++) {
        float4 wv = *(const float4*)&Ws[k][cg * 4];
        #pragma unroll
        for (int i = 0; i < 4; i++) {
            float a = As[rg * 4 + i][k];
            acc[i][0] = fmaf(a, wv.x, acc[i][0]);
            acc[i][1] = fmaf(a, wv.y, acc[i][1]);
            acc[i][2] = fmaf(a, wv.z, acc[i][2]);
            acc[i][3] = fmaf(a, wv.w, acc[i][3]);
        }
    }

    float4 bv = *(const float4*)&b[cg * 4];

    #pragma unroll
    for (int i = 0; i < 4; i++) {
        int gr = r0 + rg * 4 + i;
        if (gr >= NN) continue;
        float d  = g_dinv[gr];
        float d2 = d * d;
        float4 lv = make_float4(acc[i][0], acc[i][1], acc[i][2], acc[i][3]);
        *(float4*)&lin[(size_t)gr * HH + cg * 4] = lv;
        // self-loop message + bias = initial value of the aggregation buffer
        float4 av = make_float4(fmaf(lv.x, d2, bv.x), fmaf(lv.y, d2, bv.y),
                                fmaf(lv.z, d2, bv.z), fmaf(lv.w, d2, bv.w));
        *(float4*)&agg[(size_t)gr * HH + cg * 4] = av;
    }
}

// ---------------- edge scatter: agg[col] += lin[row] * norm -------------------
// 16 threads per edge, float4 each -> coalesced 256B gather per edge.
__global__ void __launch_bounds__(256)
scatter_kernel(const float* __restrict__ lin, const int* __restrict__ row,
               const int* __restrict__ col, float* __restrict__ agg) {
    long long idx = (long long)blockIdx.x * blockDim.x + threadIdx.x;
    int e = (int)(idx >> 4);
    if (e >= EE) return;
    int c = (int)(idx & 15);
    int r = row[e], t = col[e];
    float nm = g_norm[e];
    float4 v = *(const float4*)(lin + (size_t)r * HH + c * 4);
    v.x *= nm; v.y *= nm; v.z *= nm; v.w *= nm;
    float* p = agg + (size_t)t * HH + c * 4;
    asm volatile("red.global.add.v4.f32 [%0], {%1, %2, %3, %4};"
                 :: "l"(p), "f"(v.x), "f"(v.y), "f"(v.z), "f"(v.w)
                 : "memory");
}

// ---------------- pooling -----------------------------------------------------
__global__ void zero_pool_kernel() {
    int i = blockIdx.x * blockDim.x + threadIdx.x;
    if (i < GG * HH) g_pool[i] = 0.0f;
    if (i < GG) g_cnt[i] = 0.0f;
}

__global__ void count_kernel(const int* __restrict__ batch) {
    int n = blockIdx.x * blockDim.x + threadIdx.x;
    if (n < NN) atomicAdd(&g_cnt[batch[n]], 1.0f);
}

__global__ void __launch_bounds__(256)
pool_kernel(const float* __restrict__ h, const int* __restrict__ batch) {
    long long idx = (long long)blockIdx.x * blockDim.x + threadIdx.x;
    int n = (int)(idx >> 4);
    if (n >= NN) return;
    int c = (int)(idx & 15);
    int g = batch[n];
    float4 v = *(const float4*)(h + (size_t)n * HH + c * 4);
    float* p = &g_pool[g * HH + c * 4];
    asm volatile("red.global.add.v4.f32 [%0], {%1, %2, %3, %4};"
                 :: "l"(p), "f"(v.x), "f"(v.y), "f"(v.z), "f"(v.w)
                 : "memory");
}

// ---------------- final linear: out[g][o] = mean_pool @ lin_W + lin_b --------
__global__ void final_kernel(const float* __restrict__ linW,
                             const float* __restrict__ linb,
                             float* __restrict__ out) {
    int g = blockIdx.x * blockDim.x + threadIdx.x;
    if (g >= GG) return;
    float inv = 1.0f / fmaxf(g_cnt[g], 1.0f);
    float a0 = 0.0f, a1 = 0.0f;
    #pragma unroll 8
    for (int f = 0; f < HH; f++) {
        float p = g_pool[g * HH + f] * inv;
        a0 = fmaf(p, linW[f * 2 + 0], a0);
        a1 = fmaf(p, linW[f * 2 + 1], a1);
    }
    out[g * 2 + 0] = a0 + linb[0];
    out[g * 2 + 1] = a1 + linb[1];
}

// ---------------- launcher ----------------------------------------------------
extern "C" void kernel_launch(void* const* d_in, const int* in_sizes, int n_in,
                              void* d_out, int out_size) {
    const float* x     = (const float*)d_in[0];
    const int*   eidx  = (const int*)d_in[1];     // [2, E]: row then col
    const int*   batch = (const int*)d_in[2];
    const float* W0    = (const float*)d_in[3];
    const float* b0    = (const float*)d_in[4];
    const float* W1    = (const float*)d_in[5];
    const float* b1    = (const float*)d_in[6];
    const float* W2    = (const float*)d_in[7];
    const float* b2    = (const float*)d_in[8];
    const float* linW  = (const float*)d_in[9];
    const float* linb  = (const float*)d_in[10];
    float* out = (float*)d_out;

    const int* row = eidx;
    const int* col = eidx + EE;

    float *bufA, *bufB;
    cudaGetSymbolAddress((void**)&bufA, g_bufA);
    cudaGetSymbolAddress((void**)&bufB, g_bufB);

    const int T = 256;
    int nb_N  = (NN + T - 1) / T;
    int nb_E  = (EE + T - 1) / T;
    int nb_sc = (int)(((long long)EE * 16 + T - 1) / T);
    int nb_pl = (int)(((long long)NN * 16 + T - 1) / T);
    int nb_gm = (NN + 63) / 64;

    // normalization
    init_deg_kernel<<<nb_N, T>>>();
    accum_deg_kernel<<<nb_E, T>>>(col);
    finish_dinv_kernel<<<nb_N, T>>>();
    compute_norm_kernel<<<nb_E, T>>>(row, col);

    // layer 0: in = x -> lin = A, agg = B
    gemm_kernel<<<nb_gm, T>>>(x, W0, b0, bufA, bufB, 0);
    scatter_kernel<<<nb_sc, T>>>(bufA, row, col, bufB);

    // layer 1: in = relu(B) -> lin = A, agg = B
    gemm_kernel<<<nb_gm, T>>>(bufB, W1, b1, bufA, bufB, 1);
    scatter_kernel<<<nb_sc, T>>>(bufA, row, col, bufB);

    // layer 2 (no relu on output): in = relu(B) -> lin = A, agg = B
    gemm_kernel<<<nb_gm, T>>>(bufB, W2, b2, bufA, bufB, 1);
    scatter_kernel<<<nb_sc, T>>>(bufA, row, col, bufB);

    // global mean pool + final linear
    zero_pool_kernel<<<(GG * HH + T - 1) / T, T>>>();
    count_kernel<<<nb_N, T>>>(batch);
    pool_kernel<<<nb_pl, T>>>(bufB, batch);
    final_kernel<<<1, GG>>>(linW, linb, out);
}

// round 3
// speedup vs baseline: 1.3483x; 1.3483x over previous
#include <cuda_runtime.h>
#include <cuda_bf16.h>
#include <cstdint>

#define NN 100000
#define EE 1600000
#define HH 64
#define GG 256
#define NB_SCAN ((NN + 255) / 256)   // 391

// ---------------- static device scratch ----------------
__device__ int   g_deg[NN];              // edge-histogram (in-degree, no self-loop)
__device__ int   g_off[NN];              // CSR row offsets (exclusive scan of deg)
__device__ int   g_cursor[NN];           // fill cursors
__device__ int   g_csr[EE];              // source node per CSR slot
__device__ int   g_bsum[512];            // scan block sums
__device__ float g_dinv[NN];             // rsqrt(deg+1)
__device__ float g_bufA[(size_t)NN * HH];   // s = lin * dinv
__device__ float g_bufB[(size_t)NN * HH];   // T = gathered sums
__device__ float g_pool[GG * HH];
__device__ float g_cnt[GG];

// ---------------- CSR build ----------------
__global__ void zero_kernel() {
    int i = blockIdx.x * blockDim.x + threadIdx.x;
    if (i < NN) g_deg[i] = 0;
    if (i < GG * HH) g_pool[i] = 0.0f;
    if (i < GG) g_cnt[i] = 0.0f;
}

__global__ void hist_kernel(const int* __restrict__ col) {
    int e = blockIdx.x * blockDim.x + threadIdx.x;
    if (e < EE) atomicAdd(&g_deg[col[e]], 1);
}

// exclusive scan, stage 1: per-block scan of 256 elems
__global__ void scan1_kernel() {
    __shared__ int sh[256];
    int t = threadIdx.x;
    int i = blockIdx.x * 256 + t;
    int v = (i < NN) ? g_deg[i] : 0;
    sh[t] = v;
    __syncthreads();
    #pragma unroll
    for (int off = 1; off < 256; off <<= 1) {
        int a = (t >= off) ? sh[t - off] : 0;
        __syncthreads();
        sh[t] += a;
        __syncthreads();
    }
    int incl = sh[t];
    if (i < NN) g_off[i] = incl - v;
    if (t == 255) g_bsum[blockIdx.x] = incl;
}

// stage 2: serial scan of block sums (391 elems, trivial)
__global__ void scan2_kernel() {
    if (threadIdx.x == 0) {
        int run = 0;
        for (int b = 0; b < NB_SCAN; b++) {
            int v = g_bsum[b];
            g_bsum[b] = run;
            run += v;
        }
    }
}

// stage 3: add block offsets; init cursors; compute dinv
__global__ void scan3_kernel() {
    int i = blockIdx.x * blockDim.x + threadIdx.x;
    if (i >= NN) return;
    int o = g_off[i] + g_bsum[i >> 8];
    g_off[i] = o;
    g_cursor[i] = o;
    g_dinv[i] = rsqrtf((float)g_deg[i] + 1.0f);
}

__global__ void fill_kernel(const int* __restrict__ row, const int* __restrict__ col) {
    int e = blockIdx.x * blockDim.x + threadIdx.x;
    if (e >= EE) return;
    int t = col[e];
    int p = atomicAdd(&g_cursor[t], 1);
    g_csr[p] = row[e];
}

// ---------------- GEMM: s = act(in) @ W * dinv[row] ----------------
// mode 0: v = in (raw x).  mode 1: v = relu(dinv[row]*in + bprev[col])
__global__ void __launch_bounds__(256)
gemm_kernel(const float* __restrict__ in, const float* __restrict__ W,
            const float* __restrict__ bprev, float* __restrict__ s, int mode) {
    __shared__ float Ws[64][64];
    __shared__ float As[64][65];

    int tid = threadIdx.x;
    int r0  = blockIdx.x * 64;

    #pragma unroll 4
    for (int i = tid; i < 64 * 64; i += 256)
        Ws[i >> 6][i & 63] = W[i];

    #pragma unroll 4
    for (int i = tid; i < 64 * 64; i += 256) {
        int rr = i >> 6, cc = i & 63;
        int gr = r0 + rr;
        float v = 0.0f;
        if (gr < NN) {
            v = in[(size_t)gr * HH + cc];
            if (mode == 1) v = fmaxf(fmaf(g_dinv[gr], v, bprev[cc]), 0.0f);
        }
        As[rr][cc] = v;
    }
    __syncthreads();

    int rg = tid >> 4;
    int cg = tid & 15;

    float acc[4][4];
    #pragma unroll
    for (int i = 0; i < 4; i++)
        #pragma unroll
        for (int j = 0; j < 4; j++) acc[i][j] = 0.0f;

    #pragma unroll 8
    for (int k = 0; k < 64; k++) {
        float4 wv = *(const float4*)&Ws[k][cg * 4];
        #pragma unroll
        for (int i = 0; i < 4; i++) {
            float a = As[rg * 4 + i][k];
            acc[i][0] = fmaf(a, wv.x, acc[i][0]);
            acc[i][1] = fmaf(a, wv.y, acc[i][1]);
            acc[i][2] = fmaf(a, wv.z, acc[i][2]);
            acc[i][3] = fmaf(a, wv.w, acc[i][3]);
        }
    }

    #pragma unroll
    for (int i = 0; i < 4; i++) {
        int gr = r0 + rg * 4 + i;
        if (gr >= NN) continue;
        float d = g_dinv[gr];
        float4 sv = make_float4(acc[i][0] * d, acc[i][1] * d,
                                acc[i][2] * d, acc[i][3] * d);
        *(float4*)&s[(size_t)gr * HH + cg * 4] = sv;
    }
}

// ---------------- gather: T[t] = s[t] + sum_{r in N(t)} s[r] ----------------
// 16 threads per node; each owns one float4 column slice.
__global__ void __launch_bounds__(256)
gather_kernel(const float* __restrict__ s, float* __restrict__ T) {
    long long idx = (long long)blockIdx.x * blockDim.x + threadIdx.x;
    int t = (int)(idx >> 4);
    if (t >= NN) return;
    int c = (int)(idx & 15);

    unsigned gmask = 0xFFFFu << (threadIdx.x & 16);

    int base = g_off[t];
    int deg  = g_deg[t];

    float4 acc = *(const float4*)(s + (size_t)t * HH + c * 4);  // self-loop

    for (int k = 0; k < deg; k += 16) {
        int rem = deg - k;
        int myidx = (c < rem) ? g_csr[base + k + c] : 0;
        if (rem >= 16) {
            #pragma unroll
            for (int j = 0; j < 16; j++) {
                int r = __shfl_sync(gmask, myidx, j, 16);
                float4 v = *(const float4*)(s + (size_t)r * HH + c * 4);
                acc.x += v.x; acc.y += v.y; acc.z += v.z; acc.w += v.w;
            }
        } else {
            for (int j = 0; j < rem; j++) {
                int r = __shfl_sync(gmask, myidx, j, 16);
                float4 v = *(const float4*)(s + (size_t)r * HH + c * 4);
                acc.x += v.x; acc.y += v.y; acc.z += v.z; acc.w += v.w;
            }
        }
    }
    *(float4*)(T + (size_t)t * HH + c * 4) = acc;
}

// ---------------- pool: mean over graphs of (dinv[n]*T[n] + b2) -------------
__global__ void __launch_bounds__(256)
pool_kernel(const float* __restrict__ T, const int* __restrict__ batch,
            const float* __restrict__ b2) {
    long long idx = (long long)blockIdx.x * blockDim.x + threadIdx.x;
    int n = (int)(idx >> 4);
    if (n >= NN) return;
    int c = (int)(idx & 15);
    int g = batch[n];
    float d = g_dinv[n];
    float4 v = *(const float4*)(T + (size_t)n * HH + c * 4);
    float4 bb = *(const float4*)&b2[c * 4];
    v.x = fmaf(d, v.x, bb.x); v.y = fmaf(d, v.y, bb.y);
    v.z = fmaf(d, v.z, bb.z); v.w = fmaf(d, v.w, bb.w);
    float* p = &g_pool[g * HH + c * 4];
    asm volatile("red.global.add.v4.f32 [%0], {%1, %2, %3, %4};"
                 :: "l"(p), "f"(v.x), "f"(v.y), "f"(v.z), "f"(v.w)
                 : "memory");
    if (c == 0) atomicAdd(&g_cnt[g], 1.0f);
}

__global__ void final_kernel(const float* __restrict__ linW,
                             const float* __restrict__ linb,
                             float* __restrict__ out) {
    int g = blockIdx.x * blockDim.x + threadIdx.x;
    if (g >= GG) return;
    float inv = 1.0f / fmaxf(g_cnt[g], 1.0f);
    float a0 = 0.0f, a1 = 0.0f;
    #pragma unroll 8
    for (int f = 0; f < HH; f++) {
        float p = g_pool[g * HH + f] * inv;
        a0 = fmaf(p, linW[f * 2 + 0], a0);
        a1 = fmaf(p, linW[f * 2 + 1], a1);
    }
    out[g * 2 + 0] = a0 + linb[0];
    out[g * 2 + 1] = a1 + linb[1];
}

// ---------------- launcher ----------------------------------------------------
extern "C" void kernel_launch(void* const* d_in, const int* in_sizes, int n_in,
                              void* d_out, int out_size) {
    const float* x     = (const float*)d_in[0];
    const int*   eidx  = (const int*)d_in[1];
    const int*   batch = (const int*)d_in[2];
    const float* W0    = (const float*)d_in[3];
    const float* b0    = (const float*)d_in[4];
    const float* W1    = (const float*)d_in[5];
    const float* b1    = (const float*)d_in[6];
    const float* W2    = (const float*)d_in[7];
    const float* b2    = (const float*)d_in[8];
    const float* linW  = (const float*)d_in[9];
    const float* linb  = (const float*)d_in[10];
    float* out = (float*)d_out;

    const int* row = eidx;
    const int* col = eidx + EE;

    float *bufA, *bufB;
    cudaGetSymbolAddress((void**)&bufA, g_bufA);
    cudaGetSymbolAddress((void**)&bufB, g_bufB);

    const int T = 256;
    int nb_N  = (NN + T - 1) / T;
    int nb_E  = (EE + T - 1) / T;
    int nb_16 = (int)(((long long)NN * 16 + T - 1) / T);
    int nb_gm = (NN + 63) / 64;

    // CSR build + dinv
    zero_kernel<<<nb_N, T>>>();
    hist_kernel<<<nb_E, T>>>(col);
    scan1_kernel<<<NB_SCAN, 256>>>();
    scan2_kernel<<<1, 32>>>();
    scan3_kernel<<<nb_N, T>>>();
    fill_kernel<<<nb_E, T>>>(row, col);

    // layer 0
    gemm_kernel<<<nb_gm, T>>>(x, W0, nullptr, bufA, 0);
    gather_kernel<<<nb_16, T>>>(bufA, bufB);
    // layer 1 (input transform: relu(dinv*T + b0))
    gemm_kernel<<<nb_gm, T>>>(bufB, W1, b0, bufA, 1);
    gather_kernel<<<nb_16, T>>>(bufA, bufB);
    // layer 2 (input transform: relu(dinv*T + b1))
    gemm_kernel<<<nb_gm, T>>>(bufB, W2, b1, bufA, 1);
    gather_kernel<<<nb_16, T>>>(bufA, bufB);

    // pool applies dinv*T + b2, then mean + final linear
    pool_kernel<<<nb_16, T>>>(bufB, batch, b2);
    final_kernel<<<1, GG>>>(linW, linb, out);
}

// round 4
// speedup vs baseline: 1.4654x; 1.0868x over previous
#include <cuda_runtime.h>
#include <cuda_bf16.h>
#include <cstdint>

#define NN 100000
#define EE 1600000
#define HH 64
#define GG 256
#define NB_SCAN ((NN + 255) / 256)   // 391

// ---------------- static device scratch ----------------
__device__ int   g_deg[NN];
__device__ int   g_off[NN];
__device__ int   g_cursor[NN];
__device__ int   g_csr[EE];
__device__ int   g_bsum[512];
__device__ float g_dinv[NN];
__device__ float g_bufA[(size_t)NN * HH];   // s = lin * dinv
__device__ float g_bufB[(size_t)NN * HH];   // T = gathered sums
__device__ float g_pool[GG * HH];
__device__ float g_cnt[GG];

// ---------------- CSR build ----------------
__global__ void zero_kernel() {
    int i = blockIdx.x * blockDim.x + threadIdx.x;
    if (i < NN) g_deg[i] = 0;
}

__global__ void hist_kernel(const int* __restrict__ col) {
    int e = blockIdx.x * blockDim.x + threadIdx.x;
    if (e < EE) atomicAdd(&g_deg[col[e]], 1);
}

// stage 1: per-block inclusive scan of 256 elems -> exclusive offsets + block sums
__global__ void scan1_kernel() {
    __shared__ int sh[256];
    int t = threadIdx.x;
    int i = blockIdx.x * 256 + t;
    int v = (i < NN) ? g_deg[i] : 0;
    sh[t] = v;
    __syncthreads();
    #pragma unroll
    for (int off = 1; off < 256; off <<= 1) {
        int a = (t >= off) ? sh[t - off] : 0;
        __syncthreads();
        sh[t] += a;
        __syncthreads();
    }
    int incl = sh[t];
    if (i < NN) g_off[i] = incl - v;
    if (t == 255) g_bsum[blockIdx.x] = incl;
}

// stage 2: parallel exclusive scan of the 391 block sums (one 512-thread block)
__global__ void scan2_kernel() {
    __shared__ int sh[512];
    int t = threadIdx.x;
    int v = (t < NB_SCAN) ? g_bsum[t] : 0;
    sh[t] = v;
    __syncthreads();
    #pragma unroll
    for (int off = 1; off < 512; off <<= 1) {
        int a = (t >= off) ? sh[t - off] : 0;
        __syncthreads();
        sh[t] += a;
        __syncthreads();
    }
    if (t < NB_SCAN) g_bsum[t] = sh[t] - v;   // exclusive
}

// stage 3: add block offsets; init cursors; compute dinv; zero pool/cnt
__global__ void scan3_kernel() {
    int i = blockIdx.x * blockDim.x + threadIdx.x;
    if (i < GG * HH) g_pool[i] = 0.0f;
    if (i < GG) g_cnt[i] = 0.0f;
    if (i >= NN) return;
    int o = g_off[i] + g_bsum[i >> 8];
    g_off[i] = o;
    g_cursor[i] = o;
    g_dinv[i] = rsqrtf((float)g_deg[i] + 1.0f);
}

__global__ void fill_kernel(const int* __restrict__ row, const int* __restrict__ col) {
    int e = blockIdx.x * blockDim.x + threadIdx.x;
    if (e >= EE) return;
    int t = col[e];
    int p = atomicAdd(&g_cursor[t], 1);
    g_csr[p] = row[e];
}

// ---------------- GEMM: s = act(in) @ W * dinv[row] ----------------
// mode 0: v = in (raw x).  mode 1: v = relu(dinv[row]*in + bprev[col])
__global__ void __launch_bounds__(256)
gemm_kernel(const float* __restrict__ in, const float* __restrict__ W,
            const float* __restrict__ bprev, float* __restrict__ s, int mode) {
    __shared__ float Ws[64][64];
    __shared__ float As[64][65];

    int tid = threadIdx.x;
    int r0  = blockIdx.x * 64;

    #pragma unroll 4
    for (int i = tid; i < 64 * 64; i += 256)
        Ws[i >> 6][i & 63] = W[i];

    #pragma unroll 4
    for (int i = tid; i < 64 * 64; i += 256) {
        int rr = i >> 6, cc = i & 63;
        int gr = r0 + rr;
        float v = 0.0f;
        if (gr < NN) {
            v = in[(size_t)gr * HH + cc];
            if (mode == 1) v = fmaxf(fmaf(g_dinv[gr], v, bprev[cc]), 0.0f);
        }
        As[rr][cc] = v;
    }
    __syncthreads();

    int rg = tid >> 4;
    int cg = tid & 15;

    float acc[4][4];
    #pragma unroll
    for (int i = 0; i < 4; i++)
        #pragma unroll
        for (int j = 0; j < 4; j++) acc[i][j] = 0.0f;

    #pragma unroll 8
    for (int k = 0; k < 64; k++) {
        float4 wv = *(const float4*)&Ws[k][cg * 4];
        #pragma unroll
        for (int i = 0; i < 4; i++) {
            float a = As[rg * 4 + i][k];
            acc[i][0] = fmaf(a, wv.x, acc[i][0]);
            acc[i][1] = fmaf(a, wv.y, acc[i][1]);
            acc[i][2] = fmaf(a, wv.z, acc[i][2]);
            acc[i][3] = fmaf(a, wv.w, acc[i][3]);
        }
    }

    #pragma unroll
    for (int i = 0; i < 4; i++) {
        int gr = r0 + rg * 4 + i;
        if (gr >= NN) continue;
        float d = g_dinv[gr];
        float4 sv = make_float4(acc[i][0] * d, acc[i][1] * d,
                                acc[i][2] * d, acc[i][3] * d);
        *(float4*)&s[(size_t)gr * HH + cg * 4] = sv;
    }
}

// ---------------- gather core ----------------
__device__ __forceinline__ float4 gather_node(const float* __restrict__ s,
                                              int t, int c, unsigned gmask) {
    int base = g_off[t];
    int deg  = g_deg[t];
    float4 acc = *(const float4*)(s + (size_t)t * HH + c * 4);  // self-loop

    for (int k = 0; k < deg; k += 16) {
        int rem = deg - k;
        int myidx = (c < rem) ? g_csr[base + k + c] : 0;
        if (rem >= 16) {
            #pragma unroll
            for (int j = 0; j < 16; j++) {
                int r = __shfl_sync(gmask, myidx, j, 16);
                float4 v = *(const float4*)(s + (size_t)r * HH + c * 4);
                acc.x += v.x; acc.y += v.y; acc.z += v.z; acc.w += v.w;
            }
        } else {
            for (int j = 0; j < rem; j++) {
                int r = __shfl_sync(gmask, myidx, j, 16);
                float4 v = *(const float4*)(s + (size_t)r * HH + c * 4);
                acc.x += v.x; acc.y += v.y; acc.z += v.z; acc.w += v.w;
            }
        }
    }
    return acc;
}

// gather: T[t] = s[t] + sum_{r in N(t)} s[r]   (layers 0,1)
__global__ void __launch_bounds__(256)
gather_kernel(const float* __restrict__ s, float* __restrict__ T) {
    long long idx = (long long)blockIdx.x * blockDim.x + threadIdx.x;
    int t = (int)(idx >> 4);
    if (t >= NN) return;
    int c = (int)(idx & 15);
    unsigned gmask = 0xFFFFu << (threadIdx.x & 16);
    float4 acc = gather_node(s, t, c, gmask);
    *(float4*)(T + (size_t)t * HH + c * 4) = acc;
}

// layer-2 gather fused with pooling: pool[batch[t]] += dinv[t]*T[t] + b2
__global__ void __launch_bounds__(256)
gather_pool_kernel(const float* __restrict__ s, const int* __restrict__ batch,
                   const float* __restrict__ b2) {
    long long idx = (long long)blockIdx.x * blockDim.x + threadIdx.x;
    int t = (int)(idx >> 4);
    if (t >= NN) return;
    int c = (int)(idx & 15);
    unsigned gmask = 0xFFFFu << (threadIdx.x & 16);
    float4 acc = gather_node(s, t, c, gmask);

    float d = g_dinv[t];
    float4 bb = *(const float4*)&b2[c * 4];
    acc.x = fmaf(d, acc.x, bb.x); acc.y = fmaf(d, acc.y, bb.y);
    acc.z = fmaf(d, acc.z, bb.z); acc.w = fmaf(d, acc.w, bb.w);

    int g = batch[t];
    float* p = &g_pool[g * HH + c * 4];
    asm volatile("red.global.add.v4.f32 [%0], {%1, %2, %3, %4};"
                 :: "l"(p), "f"(acc.x), "f"(acc.y), "f"(acc.z), "f"(acc.w)
                 : "memory");
    if (c == 0) atomicAdd(&g_cnt[g], 1.0f);
}

__global__ void final_kernel(const float* __restrict__ linW,
                             const float* __restrict__ linb,
                             float* __restrict__ out) {
    int g = blockIdx.x * blockDim.x + threadIdx.x;
    if (g >= GG) return;
    float inv = 1.0f / fmaxf(g_cnt[g], 1.0f);
    float a0 = 0.0f, a1 = 0.0f;
    #pragma unroll 8
    for (int f = 0; f < HH; f++) {
        float p = g_pool[g * HH + f] * inv;
        a0 = fmaf(p, linW[f * 2 + 0], a0);
        a1 = fmaf(p, linW[f * 2 + 1], a1);
    }
    out[g * 2 + 0] = a0 + linb[0];
    out[g * 2 + 1] = a1 + linb[1];
}

// ---------------- launcher ----------------------------------------------------
extern "C" void kernel_launch(void* const* d_in, const int* in_sizes, int n_in,
                              void* d_out, int out_size) {
    const float* x     = (const float*)d_in[0];
    const int*   eidx  = (const int*)d_in[1];
    const int*   batch = (const int*)d_in[2];
    const float* W0    = (const float*)d_in[3];
    const float* b0    = (const float*)d_in[4];
    const float* W1    = (const float*)d_in[5];
    const float* b1    = (const float*)d_in[6];
    const float* W2    = (const float*)d_in[7];
    const float* b2    = (const float*)d_in[8];
    const float* linW  = (const float*)d_in[9];
    const float* linb  = (const float*)d_in[10];
    float* out = (float*)d_out;

    const int* row = eidx;
    const int* col = eidx + EE;

    float *bufA, *bufB;
    cudaGetSymbolAddress((void**)&bufA, g_bufA);
    cudaGetSymbolAddress((void**)&bufB, g_bufB);

    const int T = 256;
    int nb_N  = (NN + T - 1) / T;
    int nb_E  = (EE + T - 1) / T;
    int nb_16 = (int)(((long long)NN * 16 + T - 1) / T);
    int nb_gm = (NN + 63) / 64;

    // CSR build + dinv (+ pool zeroing folded into scan3)
    zero_kernel<<<nb_N, T>>>();
    hist_kernel<<<nb_E, T>>>(col);
    scan1_kernel<<<NB_SCAN, 256>>>();
    scan2_kernel<<<1, 512>>>();
    scan3_kernel<<<nb_N, T>>>();
    fill_kernel<<<nb_E, T>>>(row, col);

    // layer 0
    gemm_kernel<<<nb_gm, T>>>(x, W0, nullptr, bufA, 0);
    gather_kernel<<<nb_16, T>>>(bufA, bufB);
    // layer 1
    gemm_kernel<<<nb_gm, T>>>(bufB, W1, b0, bufA, 1);
    gather_kernel<<<nb_16, T>>>(bufA, bufB);
    // layer 2: gather fused with mean-pool accumulation
    gemm_kernel<<<nb_gm, T>>>(bufB, W2, b1, bufA, 1);
    gather_pool_kernel<<<nb_16, T>>>(bufA, batch, b2);

    final_kernel<<<1, GG>>>(linW, linb, out);
}

// round 5
// speedup vs baseline: 1.4766x; 1.0077x over previous
#include <cuda_runtime.h>
#include <cuda_bf16.h>
#include <cstdint>

#define NN 100000
#define EE 1600000
#define HH 64
#define GG 256
#define NB_SCAN ((NN + 255) / 256)   // 391

// ---------------- static device scratch ----------------
__device__ int   g_deg[NN];
__device__ int   g_off[NN];
__device__ int   g_cursor[NN];
__device__ int   g_csr[EE];
__device__ int   g_bsum[512];
__device__ float g_dinv[NN];
__device__ float g_bufA[(size_t)NN * HH];
__device__ float g_bufB[(size_t)NN * HH];
__device__ float g_pool[GG * HH];
__device__ float g_cnt[GG];

// ---------------- CSR build ----------------
__global__ void zero_kernel() {
    int i = blockIdx.x * blockDim.x + threadIdx.x;
    if (i < NN) g_deg[i] = 0;
}

__global__ void hist_kernel(const int* __restrict__ col) {
    int e = blockIdx.x * blockDim.x + threadIdx.x;
    if (e < EE) atomicAdd(&g_deg[col[e]], 1);
}

__global__ void scan1_kernel() {
    __shared__ int sh[256];
    int t = threadIdx.x;
    int i = blockIdx.x * 256 + t;
    int v = (i < NN) ? g_deg[i] : 0;
    sh[t] = v;
    __syncthreads();
    #pragma unroll
    for (int off = 1; off < 256; off <<= 1) {
        int a = (t >= off) ? sh[t - off] : 0;
        __syncthreads();
        sh[t] += a;
        __syncthreads();
    }
    int incl = sh[t];
    if (i < NN) g_off[i] = incl - v;
    if (t == 255) g_bsum[blockIdx.x] = incl;
}

__global__ void scan2_kernel() {
    __shared__ int sh[512];
    int t = threadIdx.x;
    int v = (t < NB_SCAN) ? g_bsum[t] : 0;
    sh[t] = v;
    __syncthreads();
    #pragma unroll
    for (int off = 1; off < 512; off <<= 1) {
        int a = (t >= off) ? sh[t - off] : 0;
        __syncthreads();
        sh[t] += a;
        __syncthreads();
    }
    if (t < NB_SCAN) g_bsum[t] = sh[t] - v;   // exclusive
}

__global__ void scan3_kernel() {
    int i = blockIdx.x * blockDim.x + threadIdx.x;
    if (i < GG * HH) g_pool[i] = 0.0f;
    if (i < GG) g_cnt[i] = 0.0f;
    if (i >= NN) return;
    int o = g_off[i] + g_bsum[i >> 8];
    g_off[i] = o;
    g_cursor[i] = o;
    g_dinv[i] = rsqrtf((float)g_deg[i] + 1.0f);
}

__global__ void fill_kernel(const int* __restrict__ row, const int* __restrict__ col) {
    int e = blockIdx.x * blockDim.x + threadIdx.x;
    if (e >= EE) return;
    int t = col[e];
    int p = atomicAdd(&g_cursor[t], 1);
    g_csr[p] = row[e];
}

// ---------------- GEMM ----------------
// mode 0: v = in (raw x); epilogue writes RAW lin (no dinv — not ready yet).
// mode 1: v = relu(dinv[row]*in + bprev[col]); epilogue writes s = lin*dinv.
__global__ void __launch_bounds__(256)
gemm_kernel(const float* __restrict__ in, const float* __restrict__ W,
            const float* __restrict__ bprev, float* __restrict__ s, int mode) {
    __shared__ float Ws[64][64];
    __shared__ float As[64][65];

    int tid = threadIdx.x;
    int r0  = blockIdx.x * 64;

    #pragma unroll 4
    for (int i = tid; i < 64 * 64; i += 256)
        Ws[i >> 6][i & 63] = W[i];

    #pragma unroll 4
    for (int i = tid; i < 64 * 64; i += 256) {
        int rr = i >> 6, cc = i & 63;
        int gr = r0 + rr;
        float v = 0.0f;
        if (gr < NN) {
            v = in[(size_t)gr * HH + cc];
            if (mode == 1) v = fmaxf(fmaf(g_dinv[gr], v, bprev[cc]), 0.0f);
        }
        As[rr][cc] = v;
    }
    __syncthreads();

    int rg = tid >> 4;
    int cg = tid & 15;

    float acc[4][4];
    #pragma unroll
    for (int i = 0; i < 4; i++)
        #pragma unroll
        for (int j = 0; j < 4; j++) acc[i][j] = 0.0f;

    #pragma unroll 8
    for (int k = 0; k < 64; k++) {
        float4 wv = *(const float4*)&Ws[k][cg * 4];
        #pragma unroll
        for (int i = 0; i < 4; i++) {
            float a = As[rg * 4 + i][k];
            acc[i][0] = fmaf(a, wv.x, acc[i][0]);
            acc[i][1] = fmaf(a, wv.y, acc[i][1]);
            acc[i][2] = fmaf(a, wv.z, acc[i][2]);
            acc[i][3] = fmaf(a, wv.w, acc[i][3]);
        }
    }

    #pragma unroll
    for (int i = 0; i < 4; i++) {
        int gr = r0 + rg * 4 + i;
        if (gr >= NN) continue;
        float d = (mode == 1) ? g_dinv[gr] : 1.0f;
        float4 sv = make_float4(acc[i][0] * d, acc[i][1] * d,
                                acc[i][2] * d, acc[i][3] * d);
        *(float4*)&s[(size_t)gr * HH + cg * 4] = sv;
    }
}

// ---------------- gather core ----------------
// SCALE_SRC=0: T[t] = s[t] + sum s[r]            (s already dinv-scaled)
// SCALE_SRC=1: T[t] = dinv[t]*lin[t] + sum dinv[r]*lin[r]  (layer 0)
template <int SCALE_SRC>
__device__ __forceinline__ float4 gather_node(const float* __restrict__ s,
                                              int t, int c, unsigned gmask) {
    int base = g_off[t];
    int deg  = g_deg[t];

    float4 acc = *(const float4*)(s + (size_t)t * HH + c * 4);  // self-loop
    if (SCALE_SRC) {
        float dt = g_dinv[t];
        acc.x *= dt; acc.y *= dt; acc.z *= dt; acc.w *= dt;
    }

    for (int k = 0; k < deg; k += 16) {
        int rem = deg - k;
        int myidx = (c < rem) ? g_csr[base + k + c] : 0;
        if (rem >= 16) {
            #pragma unroll
            for (int j = 0; j < 16; j++) {
                int r = __shfl_sync(gmask, myidx, j, 16);
                float4 v = *(const float4*)(s + (size_t)r * HH + c * 4);
                if (SCALE_SRC) {
                    float dr = g_dinv[r];
                    acc.x = fmaf(dr, v.x, acc.x); acc.y = fmaf(dr, v.y, acc.y);
                    acc.z = fmaf(dr, v.z, acc.z); acc.w = fmaf(dr, v.w, acc.w);
                } else {
                    acc.x += v.x; acc.y += v.y; acc.z += v.z; acc.w += v.w;
                }
            }
        } else {
            for (int j = 0; j < rem; j++) {
                int r = __shfl_sync(gmask, myidx, j, 16);
                float4 v = *(const float4*)(s + (size_t)r * HH + c * 4);
                if (SCALE_SRC) {
                    float dr = g_dinv[r];
                    acc.x = fmaf(dr, v.x, acc.x); acc.y = fmaf(dr, v.y, acc.y);
                    acc.z = fmaf(dr, v.z, acc.z); acc.w = fmaf(dr, v.w, acc.w);
                } else {
                    acc.x += v.x; acc.y += v.y; acc.z += v.z; acc.w += v.w;
                }
            }
        }
    }
    return acc;
}

template <int SCALE_SRC>
__global__ void __launch_bounds__(256)
gather_kernel(const float* __restrict__ s, float* __restrict__ T) {
    long long idx = (long long)blockIdx.x * blockDim.x + threadIdx.x;
    int t = (int)(idx >> 4);
    if (t >= NN) return;
    int c = (int)(idx & 15);
    unsigned gmask = 0xFFFFu << (threadIdx.x & 16);
    float4 acc = gather_node<SCALE_SRC>(s, t, c, gmask);
    *(float4*)(T + (size_t)t * HH + c * 4) = acc;
}

__global__ void __launch_bounds__(256)
gather_pool_kernel(const float* __restrict__ s, const int* __restrict__ batch,
                   const float* __restrict__ b2) {
    long long idx = (long long)blockIdx.x * blockDim.x + threadIdx.x;
    int t = (int)(idx >> 4);
    if (t >= NN) return;
    int c = (int)(idx & 15);
    unsigned gmask = 0xFFFFu << (threadIdx.x & 16);
    float4 acc = gather_node<0>(s, t, c, gmask);

    float d = g_dinv[t];
    float4 bb = *(const float4*)&b2[c * 4];
    acc.x = fmaf(d, acc.x, bb.x); acc.y = fmaf(d, acc.y, bb.y);
    acc.z = fmaf(d, acc.z, bb.z); acc.w = fmaf(d, acc.w, bb.w);

    int g = batch[t];
    float* p = &g_pool[g * HH + c * 4];
    asm volatile("red.global.add.v4.f32 [%0], {%1, %2, %3, %4};"
                 :: "l"(p), "f"(acc.x), "f"(acc.y), "f"(acc.z), "f"(acc.w)
                 : "memory");
    if (c == 0) atomicAdd(&g_cnt[g], 1.0f);
}

__global__ void final_kernel(const float* __restrict__ linW,
                             const float* __restrict__ linb,
                             float* __restrict__ out) {
    int g = blockIdx.x * blockDim.x + threadIdx.x;
    if (g >= GG) return;
    float inv = 1.0f / fmaxf(g_cnt[g], 1.0f);
    float a0 = 0.0f, a1 = 0.0f;
    #pragma unroll 8
    for (int f = 0; f < HH; f++) {
        float p = g_pool[g * HH + f] * inv;
        a0 = fmaf(p, linW[f * 2 + 0], a0);
        a1 = fmaf(p, linW[f * 2 + 1], a1);
    }
    out[g * 2 + 0] = a0 + linb[0];
    out[g * 2 + 1] = a1 + linb[1];
}

// ---------------- launcher ----------------------------------------------------
extern "C" void kernel_launch(void* const* d_in, const int* in_sizes, int n_in,
                              void* d_out, int out_size) {
    const float* x     = (const float*)d_in[0];
    const int*   eidx  = (const int*)d_in[1];
    const int*   batch = (const int*)d_in[2];
    const float* W0    = (const float*)d_in[3];
    const float* b0    = (const float*)d_in[4];
    const float* W1    = (const float*)d_in[5];
    const float* b1    = (const float*)d_in[6];
    const float* W2    = (const float*)d_in[7];
    const float* b2    = (const float*)d_in[8];
    const float* linW  = (const float*)d_in[9];
    const float* linb  = (const float*)d_in[10];
    float* out = (float*)d_out;

    const int* row = eidx;
    const int* col = eidx + EE;

    float *bufA, *bufB;
    cudaGetSymbolAddress((void**)&bufA, g_bufA);
    cudaGetSymbolAddress((void**)&bufB, g_bufB);

    // One-time host objects (created on the pre-capture correctness call).
    static cudaStream_t s1 = nullptr;
    static cudaEvent_t evFork = nullptr, evCsr = nullptr;
    if (s1 == nullptr) {
        cudaStreamCreateWithFlags(&s1, cudaStreamNonBlocking);
        cudaEventCreateWithFlags(&evFork, cudaEventDisableTiming);
        cudaEventCreateWithFlags(&evCsr, cudaEventDisableTiming);
    }

    const int T = 256;
    int nb_N  = (NN + T - 1) / T;
    int nb_E  = (EE + T - 1) / T;
    int nb_16 = (int)(((long long)NN * 16 + T - 1) / T);
    int nb_gm = (NN + 63) / 64;

    // Fork: CSR build on side stream, layer-0 GEMM (raw lin) on main stream.
    cudaEventRecord(evFork, 0);
    cudaStreamWaitEvent(s1, evFork, 0);

    zero_kernel<<<nb_N, T, 0, s1>>>();
    hist_kernel<<<nb_E, T, 0, s1>>>(col);
    scan1_kernel<<<NB_SCAN, 256, 0, s1>>>();
    scan2_kernel<<<1, 512, 0, s1>>>();
    scan3_kernel<<<nb_N, T, 0, s1>>>();
    fill_kernel<<<nb_E, T, 0, s1>>>(row, col);
    cudaEventRecord(evCsr, s1);

    gemm_kernel<<<nb_gm, T>>>(x, W0, nullptr, bufA, 0);   // raw lin (no dinv)

    // Join: gather0 needs both lin and CSR/dinv.
    cudaStreamWaitEvent(0, evCsr, 0);

    // layer 0: per-source dinv applied inside the gather
    gather_kernel<1><<<nb_16, T>>>(bufA, bufB);
    // layer 1
    gemm_kernel<<<nb_gm, T>>>(bufB, W1, b0, bufA, 1);
    gather_kernel<0><<<nb_16, T>>>(bufA, bufB);
    // layer 2: gather fused with mean-pool accumulation
    gemm_kernel<<<nb_gm, T>>>(bufB, W2, b1, bufA, 1);
    gather_pool_kernel<<<nb_16, T>>>(bufA, batch, b2);

    final_kernel<<<1, GG>>>(linW, linb, out);
}

// round 6
// speedup vs baseline: 1.5811x; 1.0708x over previous
#include <cuda_runtime.h>
#include <cuda_fp16.h>
#include <cstdint>

#define NN 100000
#define EE 1600000
#define HH 64
#define GG 256
#define NB_SCAN ((NN + 255) / 256)   // 391

// ---------------- static device scratch ----------------
__device__ int   g_deg[NN];
__device__ int   g_off[NN];
__device__ int   g_cursor[NN];
__device__ int   g_csr[EE];
__device__ int   g_bsum[512];
__device__ float g_dinv[NN];
__device__ __align__(16) __half g_bufA[(size_t)NN * HH];   // s (fp16 messages)
__device__ float g_bufB[(size_t)NN * HH];                  // T (fp32 gathered sums)
__device__ float g_pool[GG * HH];
__device__ float g_cnt[GG];

// ---------------- CSR build ----------------
__global__ void zero_kernel() {
    int i = blockIdx.x * blockDim.x + threadIdx.x;
    if (i < NN) g_deg[i] = 0;
}

__global__ void hist_kernel(const int* __restrict__ col) {
    int e = blockIdx.x * blockDim.x + threadIdx.x;
    if (e < EE) atomicAdd(&g_deg[col[e]], 1);
}

// stage 1: per-block inclusive scan -> exclusive offsets + block totals
__global__ void scan1_kernel() {
    __shared__ int sh[256];
    int t = threadIdx.x;
    int i = blockIdx.x * 256 + t;
    int v = (i < NN) ? g_deg[i] : 0;
    sh[t] = v;
    __syncthreads();
    #pragma unroll
    for (int off = 1; off < 256; off <<= 1) {
        int a = (t >= off) ? sh[t - off] : 0;
        __syncthreads();
        sh[t] += a;
        __syncthreads();
    }
    int incl = sh[t];
    if (i < NN) g_off[i] = incl - v;
    if (t == 255) g_bsum[blockIdx.x] = incl;   // block total
}

// stage 2 (merged): each block reduces its own prefix over the 391 block totals,
// then finalizes offsets / cursors / dinv, and zeroes pool/cnt.
__global__ void scan3_kernel() {
    __shared__ int red[256];
    int t = threadIdx.x;
    int b = blockIdx.x;

    int part = 0;
    for (int j = t; j < b; j += 256) part += g_bsum[j];
    red[t] = part;
    __syncthreads();
    #pragma unroll
    for (int o = 128; o > 0; o >>= 1) {
        if (t < o) red[t] += red[t + o];
        __syncthreads();
    }
    int pre = red[0];

    int i = b * 256 + t;
    if (i < GG * HH) g_pool[i] = 0.0f;
    if (i < GG) g_cnt[i] = 0.0f;
    if (i >= NN) return;
    int o = g_off[i] + pre;
    g_off[i] = o;
    g_cursor[i] = o;
    g_dinv[i] = rsqrtf((float)g_deg[i] + 1.0f);
}

__global__ void fill_kernel(const int* __restrict__ row, const int* __restrict__ col) {
    int e = blockIdx.x * blockDim.x + threadIdx.x;
    if (e >= EE) return;
    int t = col[e];
    int p = atomicAdd(&g_cursor[t], 1);
    g_csr[p] = row[e];
}

// ---------------- GEMM ----------------
// mode 0: v = in (raw x); epilogue writes RAW lin in fp16 (no dinv — built concurrently).
// mode 1: v = relu(dinv[row]*in + bprev[col]); epilogue writes s = lin*dinv in fp16.
__global__ void __launch_bounds__(256)
gemm_kernel(const float* __restrict__ in, const float* __restrict__ W,
            const float* __restrict__ bprev, __half* __restrict__ s, int mode) {
    __shared__ float Ws[64][64];
    __shared__ float As[64][65];

    int tid = threadIdx.x;
    int r0  = blockIdx.x * 64;

    #pragma unroll 4
    for (int i = tid; i < 64 * 64; i += 256)
        Ws[i >> 6][i & 63] = W[i];

    #pragma unroll 4
    for (int i = tid; i < 64 * 64; i += 256) {
        int rr = i >> 6, cc = i & 63;
        int gr = r0 + rr;
        float v = 0.0f;
        if (gr < NN) {
            v = in[(size_t)gr * HH + cc];
            if (mode == 1) v = fmaxf(fmaf(g_dinv[gr], v, bprev[cc]), 0.0f);
        }
        As[rr][cc] = v;
    }
    __syncthreads();

    int rg = tid >> 4;
    int cg = tid & 15;

    float acc[4][4];
    #pragma unroll
    for (int i = 0; i < 4; i++)
        #pragma unroll
        for (int j = 0; j < 4; j++) acc[i][j] = 0.0f;

    #pragma unroll 8
    for (int k = 0; k < 64; k++) {
        float4 wv = *(const float4*)&Ws[k][cg * 4];
        #pragma unroll
        for (int i = 0; i < 4; i++) {
            float a = As[rg * 4 + i][k];
            acc[i][0] = fmaf(a, wv.x, acc[i][0]);
            acc[i][1] = fmaf(a, wv.y, acc[i][1]);
            acc[i][2] = fmaf(a, wv.z, acc[i][2]);
            acc[i][3] = fmaf(a, wv.w, acc[i][3]);
        }
    }

    #pragma unroll
    for (int i = 0; i < 4; i++) {
        int gr = r0 + rg * 4 + i;
        if (gr >= NN) continue;
        float d = (mode == 1) ? g_dinv[gr] : 1.0f;
        __half2 h0 = __floats2half2_rn(acc[i][0] * d, acc[i][1] * d);
        __half2 h1 = __floats2half2_rn(acc[i][2] * d, acc[i][3] * d);
        uint2 u;
        u.x = *(unsigned*)&h0;
        u.y = *(unsigned*)&h1;
        *(uint2*)&s[(size_t)gr * HH + cg * 4] = u;
    }
}

// ---------------- gather core (fp16 messages, fp32 accumulation) ----------------
__device__ __forceinline__ float4 h4load(const __half* __restrict__ s, size_t off) {
    uint2 u = *(const uint2*)(s + off);
    __half2 h0 = *(__half2*)&u.x;
    __half2 h1 = *(__half2*)&u.y;
    float2 f0 = __half22float2(h0);
    float2 f1 = __half22float2(h1);
    return make_float4(f0.x, f0.y, f1.x, f1.y);
}

// SCALE_SRC=0: T[t] = s[t] + sum s[r]                    (s already dinv-scaled)
// SCALE_SRC=1: T[t] = dinv[t]*lin[t] + sum dinv[r]*lin[r] (layer 0, raw lin)
template <int SCALE_SRC>
__device__ __forceinline__ float4 gather_node(const __half* __restrict__ s,
                                              int t, int c, unsigned gmask) {
    int base = g_off[t];
    int deg  = g_deg[t];

    float4 acc = h4load(s, (size_t)t * HH + c * 4);   // self-loop
    if (SCALE_SRC) {
        float dt = g_dinv[t];
        acc.x *= dt; acc.y *= dt; acc.z *= dt; acc.w *= dt;
    }

    for (int k = 0; k < deg; k += 16) {
        int rem = deg - k;
        int myidx = (c < rem) ? g_csr[base + k + c] : 0;
        if (rem >= 16) {
            #pragma unroll
            for (int j = 0; j < 16; j++) {
                int r = __shfl_sync(gmask, myidx, j, 16);
                float4 v = h4load(s, (size_t)r * HH + c * 4);
                if (SCALE_SRC) {
                    float dr = g_dinv[r];
                    acc.x = fmaf(dr, v.x, acc.x); acc.y = fmaf(dr, v.y, acc.y);
                    acc.z = fmaf(dr, v.z, acc.z); acc.w = fmaf(dr, v.w, acc.w);
                } else {
                    acc.x += v.x; acc.y += v.y; acc.z += v.z; acc.w += v.w;
                }
            }
        } else {
            for (int j = 0; j < rem; j++) {
                int r = __shfl_sync(gmask, myidx, j, 16);
                float4 v = h4load(s, (size_t)r * HH + c * 4);
                if (SCALE_SRC) {
                    float dr = g_dinv[r];
                    acc.x = fmaf(dr, v.x, acc.x); acc.y = fmaf(dr, v.y, acc.y);
                    acc.z = fmaf(dr, v.z, acc.z); acc.w = fmaf(dr, v.w, acc.w);
                } else {
                    acc.x += v.x; acc.y += v.y; acc.z += v.z; acc.w += v.w;
                }
            }
        }
    }
    return acc;
}

template <int SCALE_SRC>
__global__ void __launch_bounds__(256)
gather_kernel(const __half* __restrict__ s, float* __restrict__ T) {
    long long idx = (long long)blockIdx.x * blockDim.x + threadIdx.x;
    int t = (int)(idx >> 4);
    if (t >= NN) return;
    int c = (int)(idx & 15);
    unsigned gmask = 0xFFFFu << (threadIdx.x & 16);
    float4 acc = gather_node<SCALE_SRC>(s, t, c, gmask);
    *(float4*)(T + (size_t)t * HH + c * 4) = acc;
}

__global__ void __launch_bounds__(256)
gather_pool_kernel(const __half* __restrict__ s, const int* __restrict__ batch,
                   const float* __restrict__ b2) {
    long long idx = (long long)blockIdx.x * blockDim.x + threadIdx.x;
    int t = (int)(idx >> 4);
    if (t >= NN) return;
    int c = (int)(idx & 15);
    unsigned gmask = 0xFFFFu << (threadIdx.x & 16);
    float4 acc = gather_node<0>(s, t, c, gmask);

    float d = g_dinv[t];
    float4 bb = *(const float4*)&b2[c * 4];
    acc.x = fmaf(d, acc.x, bb.x); acc.y = fmaf(d, acc.y, bb.y);
    acc.z = fmaf(d, acc.z, bb.z); acc.w = fmaf(d, acc.w, bb.w);

    int g = batch[t];
    float* p = &g_pool[g * HH + c * 4];
    asm volatile("red.global.add.v4.f32 [%0], {%1, %2, %3, %4};"
                 :: "l"(p), "f"(acc.x), "f"(acc.y), "f"(acc.z), "f"(acc.w)
                 : "memory");
    if (c == 0) atomicAdd(&g_cnt[g], 1.0f);
}

__global__ void final_kernel(const float* __restrict__ linW,
                             const float* __restrict__ linb,
                             float* __restrict__ out) {
    int g = blockIdx.x * blockDim.x + threadIdx.x;
    if (g >= GG) return;
    float inv = 1.0f / fmaxf(g_cnt[g], 1.0f);
    float a0 = 0.0f, a1 = 0.0f;
    #pragma unroll 8
    for (int f = 0; f < HH; f++) {
        float p = g_pool[g * HH + f] * inv;
        a0 = fmaf(p, linW[f * 2 + 0], a0);
        a1 = fmaf(p, linW[f * 2 + 1], a1);
    }
    out[g * 2 + 0] = a0 + linb[0];
    out[g * 2 + 1] = a1 + linb[1];
}

// ---------------- launcher ----------------------------------------------------
extern "C" void kernel_launch(void* const* d_in, const int* in_sizes, int n_in,
                              void* d_out, int out_size) {
    const float* x     = (const float*)d_in[0];
    const int*   eidx  = (const int*)d_in[1];
    const int*   batch = (const int*)d_in[2];
    const float* W0    = (const float*)d_in[3];
    const float* b0    = (const float*)d_in[4];
    const float* W1    = (const float*)d_in[5];
    const float* b1    = (const float*)d_in[6];
    const float* W2    = (const float*)d_in[7];
    const float* b2    = (const float*)d_in[8];
    const float* linW  = (const float*)d_in[9];
    const float* linb  = (const float*)d_in[10];
    float* out = (float*)d_out;

    const int* row = eidx;
    const int* col = eidx + EE;

    __half* bufA;
    float*  bufB;
    cudaGetSymbolAddress((void**)&bufA, g_bufA);
    cudaGetSymbolAddress((void**)&bufB, g_bufB);

    static cudaStream_t s1 = nullptr;
    static cudaEvent_t evFork = nullptr, evCsr = nullptr;
    if (s1 == nullptr) {
        cudaStreamCreateWithFlags(&s1, cudaStreamNonBlocking);
        cudaEventCreateWithFlags(&evFork, cudaEventDisableTiming);
        cudaEventCreateWithFlags(&evCsr, cudaEventDisableTiming);
    }

    const int T = 256;
    int nb_N  = (NN + T - 1) / T;
    int nb_E  = (EE + T - 1) / T;
    int nb_16 = (int)(((long long)NN * 16 + T - 1) / T);
    int nb_gm = (NN + 63) / 64;

    // Fork: CSR build on side stream, layer-0 GEMM (raw lin) on main stream.
    cudaEventRecord(evFork, 0);
    cudaStreamWaitEvent(s1, evFork, 0);

    zero_kernel<<<nb_N, T, 0, s1>>>();
    hist_kernel<<<nb_E, T, 0, s1>>>(col);
    scan1_kernel<<<NB_SCAN, 256, 0, s1>>>();
    scan3_kernel<<<nb_N, T, 0, s1>>>();   // merged scan2+scan3
    fill_kernel<<<nb_E, T, 0, s1>>>(row, col);
    cudaEventRecord(evCsr, s1);

    gemm_kernel<<<nb_gm, T>>>(x, W0, nullptr, bufA, 0);   // raw lin (no dinv)

    cudaStreamWaitEvent(0, evCsr, 0);

    // layer 0: per-source dinv applied inside the gather
    gather_kernel<1><<<nb_16, T>>>(bufA, bufB);
    // layer 1
    gemm_kernel<<<nb_gm, T>>>(bufB, W1, b0, bufA, 1);
    gather_kernel<0><<<nb_16, T>>>(bufA, bufB);
    // layer 2: gather fused with mean-pool accumulation
    gemm_kernel<<<nb_gm, T>>>(bufB, W2, b1, bufA, 1);
    gather_pool_kernel<<<nb_16, T>>>(bufA, batch, b2);

    final_kernel<<<1, GG>>>(linW, linb, out);
}

// round 8
// speedup vs baseline: 1.8794x; 1.1886x over previous
#include <cuda_runtime.h>
#include <cuda_fp16.h>
#include <cstdint>

#define NN 100000
#define EE 1600000
#define HH 64
#define GG 256
#define NB_SCAN ((NN + 255) / 256)   // 391

// ---------------- static device scratch ----------------
__device__ int   g_deg[NN];
__device__ int   g_off[NN];
__device__ int   g_cursor[NN];
__device__ int   g_csr[EE];
__device__ int   g_bsum[512];
__device__ float g_dinv[NN];
__device__ __align__(16) __half g_bufA[(size_t)NN * HH];   // s (fp16 messages)
__device__ __align__(16) __half g_bufB[(size_t)NN * HH];   // T (fp16 gathered sums)
__device__ float g_pool[GG * HH];
__device__ float g_cnt[GG];

// ---------------- CSR build ----------------
__global__ void zero_kernel() {
    int i = blockIdx.x * blockDim.x + threadIdx.x;
    if (i < NN) g_deg[i] = 0;
}

__global__ void hist_kernel(const int* __restrict__ col) {
    int e = blockIdx.x * blockDim.x + threadIdx.x;
    if (e < EE) atomicAdd(&g_deg[col[e]], 1);
}

__global__ void scan1_kernel() {
    __shared__ int sh[256];
    int t = threadIdx.x;
    int i = blockIdx.x * 256 + t;
    int v = (i < NN) ? g_deg[i] : 0;
    sh[t] = v;
    __syncthreads();
    #pragma unroll
    for (int off = 1; off < 256; off <<= 1) {
        int a = (t >= off) ? sh[t - off] : 0;
        __syncthreads();
        sh[t] += a;
        __syncthreads();
    }
    int incl = sh[t];
    if (i < NN) g_off[i] = incl - v;
    if (t == 255) g_bsum[blockIdx.x] = incl;
}

// merged scan2+scan3: each block reduces its prefix over block totals, finalizes.
__global__ void scan3_kernel() {
    __shared__ int red[256];
    int t = threadIdx.x;
    int b = blockIdx.x;

    int part = 0;
    for (int j = t; j < b; j += 256) part += g_bsum[j];
    red[t] = part;
    __syncthreads();
    #pragma unroll
    for (int o = 128; o > 0; o >>= 1) {
        if (t < o) red[t] += red[t + o];
        __syncthreads();
    }
    int pre = red[0];

    int i = b * 256 + t;
    if (i < GG * HH) g_pool[i] = 0.0f;
    if (i < GG) g_cnt[i] = 0.0f;
    if (i >= NN) return;
    int o = g_off[i] + pre;
    g_off[i] = o;
    g_cursor[i] = o;
    g_dinv[i] = rsqrtf((float)g_deg[i] + 1.0f);
}

__global__ void fill_kernel(const int* __restrict__ row, const int* __restrict__ col) {
    int e = blockIdx.x * blockDim.x + threadIdx.x;
    if (e >= EE) return;
    int t = col[e];
    int p = atomicAdd(&g_cursor[t], 1);
    g_csr[p] = row[e];
}

// ---------------- tensor-core GEMM ----------------
// C[128 x 64] = A_tile @ W, HMMA m16n8k16, fp32 accum, fp16 in/out.
// MODE 0: input fp32 (raw x), epilogue d=1 (raw lin out; dinv applied in gather<1>).
// MODE 1: input fp16 T, tile-load transform relu(dinv*T + bprev), epilogue *dinv.
template <int MODE>
__global__ void __launch_bounds__(256)
gemm_tc_kernel(const void* __restrict__ in_, const float* __restrict__ W,
               const float* __restrict__ bprev, __half* __restrict__ s) {
    __shared__ __half As[128][72];   // stride 72 halves (144B): conflict-free ldmatrix
    __shared__ __half Ws[64][72];

    int tid = threadIdx.x;
    int r0  = blockIdx.x * 128;

    // W -> fp16 smem
    #pragma unroll 4
    for (int i = tid; i < 64 * 64; i += 256)
        Ws[i >> 6][i & 63] = __float2half(W[i]);

    // A tile -> fp16 smem (fused input transform)
    #pragma unroll 2
    for (int i = tid; i < 128 * 16; i += 256) {
        int rr = i >> 4, cg = i & 15;
        int gr = r0 + rr;
        float4 v = make_float4(0.f, 0.f, 0.f, 0.f);
        if (gr < NN) {
            if (MODE == 0) {
                v = *(const float4*)((const float*)in_ + (size_t)gr * HH + cg * 4);
            } else {
                const __half* T = (const __half*)in_;
                uint2 u = *(const uint2*)(T + (size_t)gr * HH + cg * 4);
                float2 f0 = __half22float2(*(__half2*)&u.x);
                float2 f1 = __half22float2(*(__half2*)&u.y);
                float d = g_dinv[gr];
                float4 bb = *(const float4*)&bprev[cg * 4];
                v.x = fmaxf(fmaf(d, f0.x, bb.x), 0.f);
                v.y = fmaxf(fmaf(d, f0.y, bb.y), 0.f);
                v.z = fmaxf(fmaf(d, f1.x, bb.z), 0.f);
                v.w = fmaxf(fmaf(d, f1.y, bb.w), 0.f);
            }
        }
        __half2 h0 = __floats2half2_rn(v.x, v.y);
        __half2 h1 = __floats2half2_rn(v.z, v.w);
        uint2 u; u.x = *(unsigned*)&h0; u.y = *(unsigned*)&h1;
        *(uint2*)&As[rr][cg * 4] = u;
    }
    __syncthreads();

    int w    = tid >> 5;
    int lane = tid & 31;
    int m0   = w * 16;

    // Preload A fragments: 4 k-steps x 4 regs
    unsigned a[4][4];
    #pragma unroll
    for (int k = 0; k < 4; k++) {
        const __half* p = &As[m0 + (lane & 15)][k * 16 + ((lane >> 4) << 3)];
        unsigned addr = (unsigned)__cvta_generic_to_shared(p);
        asm volatile("ldmatrix.sync.aligned.m8n8.x4.shared.b16 {%0,%1,%2,%3}, [%4];"
                     : "=r"(a[k][0]), "=r"(a[k][1]), "=r"(a[k][2]), "=r"(a[k][3])
                     : "r"(addr));
    }

    int g = lane >> 2, t4 = lane & 3;
    int gr0 = r0 + m0 + g;
    int gr1 = gr0 + 8;
    float d0 = 1.0f, d1 = 1.0f;
    if (MODE == 1) {
        d0 = (gr0 < NN) ? g_dinv[gr0] : 1.0f;
        d1 = (gr1 < NN) ? g_dinv[gr1] : 1.0f;
    }

    #pragma unroll
    for (int n = 0; n < 8; n++) {
        float c0 = 0.f, c1 = 0.f, c2 = 0.f, c3 = 0.f;
        #pragma unroll
        for (int k = 0; k < 4; k++) {
            const __half* p = &Ws[k * 16 + (lane & 15)][n * 8];
            unsigned addr = (unsigned)__cvta_generic_to_shared(p);
            unsigned b0, b1;
            asm volatile("ldmatrix.sync.aligned.m8n8.x2.trans.shared.b16 {%0,%1}, [%2];"
                         : "=r"(b0), "=r"(b1) : "r"(addr));
            asm volatile("mma.sync.aligned.m16n8k16.row.col.f32.f16.f16.f32 "
                         "{%0,%1,%2,%3}, {%4,%5,%6,%7}, {%8,%9}, {%0,%1,%2,%3};"
                         : "+f"(c0), "+f"(c1), "+f"(c2), "+f"(c3)
                         : "r"(a[k][0]), "r"(a[k][1]), "r"(a[k][2]), "r"(a[k][3]),
                           "r"(b0), "r"(b1));
        }
        int colb = n * 8 + 2 * t4;
        if (gr0 < NN) {
            __half2 h = __floats2half2_rn(c0 * d0, c1 * d0);
            *(__half2*)&s[(size_t)gr0 * HH + colb] = h;
        }
        if (gr1 < NN) {
            __half2 h = __floats2half2_rn(c2 * d1, c3 * d1);
            *(__half2*)&s[(size_t)gr1 * HH + colb] = h;
        }
    }
}

// ---------------- gather core (fp16 messages, fp32 accumulation) ----------------
__device__ __forceinline__ float4 h4load(const __half* __restrict__ s, size_t off) {
    uint2 u = *(const uint2*)(s + off);
    float2 f0 = __half22float2(*(__half2*)&u.x);
    float2 f1 = __half22float2(*(__half2*)&u.y);
    return make_float4(f0.x, f0.y, f1.x, f1.y);
}

// SCALE_SRC=0: T[t] = s[t] + sum s[r]                     (s already dinv-scaled)
// SCALE_SRC=1: T[t] = dinv[t]*lin[t] + sum dinv[r]*lin[r]  (layer 0, raw lin)
template <int SCALE_SRC>
__device__ __forceinline__ float4 gather_node(const __half* __restrict__ s,
                                              int t, int c, unsigned gmask) {
    int base = g_off[t];
    int deg  = g_deg[t];

    float4 acc = h4load(s, (size_t)t * HH + c * 4);
    if (SCALE_SRC) {
        float dt = g_dinv[t];
        acc.x *= dt; acc.y *= dt; acc.z *= dt; acc.w *= dt;
    }

    for (int k = 0; k < deg; k += 16) {
        int rem = deg - k;
        int myidx = (c < rem) ? g_csr[base + k + c] : 0;
        if (rem >= 16) {
            #pragma unroll
            for (int j = 0; j < 16; j++) {
                int r = __shfl_sync(gmask, myidx, j, 16);
                float4 v = h4load(s, (size_t)r * HH + c * 4);
                if (SCALE_SRC) {
                    float dr = g_dinv[r];
                    acc.x = fmaf(dr, v.x, acc.x); acc.y = fmaf(dr, v.y, acc.y);
                    acc.z = fmaf(dr, v.z, acc.z); acc.w = fmaf(dr, v.w, acc.w);
                } else {
                    acc.x += v.x; acc.y += v.y; acc.z += v.z; acc.w += v.w;
                }
            }
        } else {
            for (int j = 0; j < rem; j++) {
                int r = __shfl_sync(gmask, myidx, j, 16);
                float4 v = h4load(s, (size_t)r * HH + c * 4);
                if (SCALE_SRC) {
                    float dr = g_dinv[r];
                    acc.x = fmaf(dr, v.x, acc.x); acc.y = fmaf(dr, v.y, acc.y);
                    acc.z = fmaf(dr, v.z, acc.z); acc.w = fmaf(dr, v.w, acc.w);
                } else {
                    acc.x += v.x; acc.y += v.y; acc.z += v.z; acc.w += v.w;
                }
            }
        }
    }
    return acc;
}

// T out in fp16
template <int SCALE_SRC>
__global__ void __launch_bounds__(256)
gather_kernel(const __half* __restrict__ s, __half* __restrict__ T) {
    long long idx = (long long)blockIdx.x * blockDim.x + threadIdx.x;
    int t = (int)(idx >> 4);
    if (t >= NN) return;
    int c = (int)(idx & 15);
    unsigned gmask = 0xFFFFu << (threadIdx.x & 16);
    float4 acc = gather_node<SCALE_SRC>(s, t, c, gmask);
    __half2 h0 = __floats2half2_rn(acc.x, acc.y);
    __half2 h1 = __floats2half2_rn(acc.z, acc.w);
    uint2 u; u.x = *(unsigned*)&h0; u.y = *(unsigned*)&h1;
    *(uint2*)(T + (size_t)t * HH + c * 4) = u;
}

__global__ void __launch_bounds__(256)
gather_pool_kernel(const __half* __restrict__ s, const int* __restrict__ batch,
                   const float* __restrict__ b2) {
    long long idx = (long long)blockIdx.x * blockDim.x + threadIdx.x;
    int t = (int)(idx >> 4);
    if (t >= NN) return;
    int c = (int)(idx & 15);
    unsigned gmask = 0xFFFFu << (threadIdx.x & 16);
    float4 acc = gather_node<0>(s, t, c, gmask);

    float d = g_dinv[t];
    float4 bb = *(const float4*)&b2[c * 4];
    acc.x = fmaf(d, acc.x, bb.x); acc.y = fmaf(d, acc.y, bb.y);
    acc.z = fmaf(d, acc.z, bb.z); acc.w = fmaf(d, acc.w, bb.w);

    int g = batch[t];
    float* p = &g_pool[g * HH + c * 4];
    asm volatile("red.global.add.v4.f32 [%0], {%1, %2, %3, %4};"
                 :: "l"(p), "f"(acc.x), "f"(acc.y), "f"(acc.z), "f"(acc.w)
                 : "memory");
    if (c == 0) atomicAdd(&g_cnt[g], 1.0f);
}

__global__ void final_kernel(const float* __restrict__ linW,
                             const float* __restrict__ linb,
                             float* __restrict__ out) {
    int g = blockIdx.x * blockDim.x + threadIdx.x;
    if (g >= GG) return;
    float inv = 1.0f / fmaxf(g_cnt[g], 1.0f);
    float a0 = 0.0f, a1 = 0.0f;
    #pragma unroll 8
    for (int f = 0; f < HH; f++) {
        float p = g_pool[g * HH + f] * inv;
        a0 = fmaf(p, linW[f * 2 + 0], a0);
        a1 = fmaf(p, linW[f * 2 + 1], a1);
    }
    out[g * 2 + 0] = a0 + linb[0];
    out[g * 2 + 1] = a1 + linb[1];
}

// ---------------- launcher ----------------------------------------------------
extern "C" void kernel_launch(void* const* d_in, const int* in_sizes, int n_in,
                              void* d_out, int out_size) {
    const float* x     = (const float*)d_in[0];
    const int*   eidx  = (const int*)d_in[1];
    const int*   batch = (const int*)d_in[2];
    const float* W0    = (const float*)d_in[3];
    const float* b0    = (const float*)d_in[4];
    const float* W1    = (const float*)d_in[5];
    const float* b1    = (const float*)d_in[6];
    const float* W2    = (const float*)d_in[7];
    const float* b2    = (const float*)d_in[8];
    const float* linW  = (const float*)d_in[9];
    const float* linb  = (const float*)d_in[10];
    float* out = (float*)d_out;

    const int* row = eidx;
    const int* col = eidx + EE;

    __half *bufA, *bufB;
    cudaGetSymbolAddress((void**)&bufA, g_bufA);
    cudaGetSymbolAddress((void**)&bufB, g_bufB);

    static cudaStream_t s1 = nullptr;
    static cudaEvent_t evFork = nullptr, evCsr = nullptr;
    if (s1 == nullptr) {
        cudaStreamCreateWithFlags(&s1, cudaStreamNonBlocking);
        cudaEventCreateWithFlags(&evFork, cudaEventDisableTiming);
        cudaEventCreateWithFlags(&evCsr, cudaEventDisableTiming);
    }

    const int T = 256;
    int nb_N  = (NN + T - 1) / T;
    int nb_E  = (EE + T - 1) / T;
    int nb_16 = (int)(((long long)NN * 16 + T - 1) / T);
    int nb_gm = (NN + 127) / 128;

    // Fork: CSR build on side stream, layer-0 GEMM (raw lin) on main stream.
    cudaEventRecord(evFork, 0);
    cudaStreamWaitEvent(s1, evFork, 0);

    zero_kernel<<<nb_N, T, 0, s1>>>();
    hist_kernel<<<nb_E, T, 0, s1>>>(col);
    scan1_kernel<<<NB_SCAN, 256, 0, s1>>>();
    scan3_kernel<<<nb_N, T, 0, s1>>>();
    fill_kernel<<<nb_E, T, 0, s1>>>(row, col);
    cudaEventRecord(evCsr, s1);

    gemm_tc_kernel<0><<<nb_gm, T>>>(x, W0, nullptr, bufA);   // raw lin (no dinv)

    cudaStreamWaitEvent(0, evCsr, 0);

    // layer 0: per-source dinv applied inside the gather
    gather_kernel<1><<<nb_16, T>>>(bufA, bufB);
    // layer 1
    gemm_tc_kernel<1><<<nb_gm, T>>>(bufB, W1, b0, bufA);
    gather_kernel<0><<<nb_16, T>>>(bufA, bufB);
    // layer 2: gather fused with mean-pool accumulation
    gemm_tc_kernel<1><<<nb_gm, T>>>(bufB, W2, b1, bufA);
    gather_pool_kernel<<<nb_16, T>>>(bufA, batch, b2);

    final_kernel<<<1, GG>>>(linW, linb, out);
}